// round 13
// baseline (speedup 1.0000x reference)
#include <cuda_runtime.h>

// FullAutoLSTM, GB300 sm_103a — persistent 2-D-tiled kernel with grid barrier.
// 128 CTAs = 16 row-tiles (64 batch rows) x 8 unit-tiles (32 hidden units).
// Weights: gate-interleaved 147KB slice per CTA (L1/L2-resident).
// c state in registers; h exchanged via L2 (__stcg/__ldcg) each step;
// one sense-counter global barrier per step. fp32 math via fma.rn.f32x2.

typedef unsigned long long ull;

#define TW   512
#define TT   1024
#define NK   288      // F(32) + H(256)
#define NB   1024
#define NH   256
#define NO   8
#define FA   24
#define BR   64       // rows per CTA
#define UT   32       // units per CTA
#define THREADS 256
#define NCTA 128
#define SMEM_BYTES 122880   // pad > 113.5KB to force 1 CTA/SM (co-residency)

__device__ float g_Wr[8 * NK * 128];      // [ut][k][local_unit][gate]
__device__ float g_hbuf[2][NB * NH];
__device__ unsigned g_barctr;
__device__ volatile unsigned g_barsense;

__device__ __forceinline__ void fma2(ull& a, ull x, ull w) {
    asm("fma.rn.f32x2 %0, %1, %2, %0;" : "+l"(a) : "l"(x), "l"(w));
}
__device__ __forceinline__ ull dup2(float v) {
    ull r; asm("mov.b64 %0, {%1, %1};" : "=l"(r) : "f"(v)); return r;
}
__device__ __forceinline__ float2 unp(ull v) {
    float2 r; asm("mov.b64 {%0, %1}, %2;" : "=f"(r.x), "=f"(r.y) : "l"(v)); return r;
}
__device__ __forceinline__ float fsig(float x) { return 1.0f / (1.0f + __expf(-x)); }
__device__ __forceinline__ float fth(float x)  { return 2.0f / (1.0f + __expf(-2.0f * x)) - 1.0f; }

// Swizzled float index of x-tile element [krow][pair p] (float2 granularity).
// XOR by (kr>>2)&31 spreads the k-strided staging stores across banks.
__device__ __forceinline__ int sxi(int kr, int p) {
    return kr * 64 + 2 * (p ^ ((kr >> 2) & 31));
}

__global__ void repack_kernel(const float* __restrict__ W_ih,
                              const float* __restrict__ W_hh) {
    int i = blockIdx.x * blockDim.x + threadIdx.x;
    if (i == 0) { g_barctr = 0; g_barsense = 0; }
    if (i >= 8 * NK * 128) return;
    int ut  = i / (NK * 128);
    int rem = i - ut * (NK * 128);
    int k   = rem >> 7;
    int c   = rem & 127;
    int l   = c >> 2;
    int g   = c & 3;
    int col = g * NH + ut * UT + l;
    g_Wr[i] = (k < 32) ? W_ih[(size_t)k * 1024 + col]
                       : W_hh[(size_t)(k - 32) * 1024 + col];
}

// Stage 64 rows x 256 units of h into the swizzled x-tile (krows 32..287).
// Warp w handles rows 8w..8w+7; coalesced 512B global loads per warp.
__device__ __forceinline__ void stage_h(float* sm, const float* hsrc,
                                        int b0, int w, int l) {
#pragma unroll
    for (int rr = 0; rr < 8; rr++) {
        int r = 8 * w + rr;
        const float4* hr = (const float4*)(hsrc + (size_t)(b0 + r) * NH);
        int p = r >> 1, hh = r & 1;
#pragma unroll
        for (int j = 0; j < 2; j++) {
            float4 v = __ldcg(&hr[l + 32 * j]);
            int kr = 32 + 4 * (l + 32 * j);          // multiple of 4
            int base = kr * 64 + 2 * (p ^ ((kr >> 2) & 31)) + hh;
            sm[base]       = v.x;   // kr..kr+3 share the swizzle value
            sm[base + 64]  = v.y;
            sm[base + 128] = v.z;
            sm[base + 192] = v.w;
        }
    }
}

// y = h @ W_out + b_out over the staged h; optionally writes output row
// (unit-tile 0) and the autoregressive feedback slots (krows 24..31).
__device__ __forceinline__ void y_pass(float* sm, const float* swout, float bo0,
                                       int t, int b0, int ut, int sprev,
                                       bool feedback, float* __restrict__ out) {
    int p = t & 31, o = t >> 5;
    ull acc = 0;
#pragma unroll 8
    for (int k = 0; k < NH; k++) {
        int kr = 32 + k;
        ull x = *(const ull*)&sm[sxi(kr, p)];
        fma2(acc, x, dup2(swout[k * NO + o]));
    }
    float2 y = unp(acc);
    y.x += bo0; y.y += bo0;
    if (ut == 0) {
        out[((size_t)(b0 + 2 * p)     * TT + sprev) * NO + o] = y.x;
        out[((size_t)(b0 + 2 * p + 1) * TT + sprev) * NO + o] = y.y;
    }
    if (feedback)
        *(float2*)&sm[sxi(24 + o, p)] = y;
}

__global__ void __launch_bounds__(THREADS, 1)
lstm_main(const float* __restrict__ c0, const float* __restrict__ h0,
          const float* __restrict__ warm, const float* __restrict__ autoin,
          const float* __restrict__ bias, const float* __restrict__ W_out,
          const float* __restrict__ b_out, float* __restrict__ out)
{
    extern __shared__ float sm[];
    float* swout = sm + NK * 64;        // [256][8] after 73728B x-tile

    const int t  = threadIdx.x;
    const int w  = t >> 5, l = t & 31;
    const int rt = blockIdx.x & 15, ut = blockIdx.x >> 4;
    const int b0 = rt * BR;
    const int U  = ut * UT + l;         // this thread's global hidden unit

    for (int i = t; i < NH * NO; i += THREADS) swout[i] = W_out[i];
    const float bi = bias[U],          bf = bias[NH + U];
    const float bg = bias[2 * NH + U], bo = bias[3 * NH + U];
    const float bo0 = __ldg(&b_out[t >> 5]);

    float cr[8];
#pragma unroll
    for (int i = 0; i < 8; i++)
        cr[i] = c0[(size_t)(b0 + 8 * w + i) * NH + U];

    const float4* wp = (const float4*)g_Wr + (size_t)ut * NK * 32 + l;

    for (int s = 0; s < TT; s++) {
        // ---- stage h_s + x_s ----
        stage_h(sm, (s == 0) ? h0 : g_hbuf[s & 1], b0, w, l);
        if (s < TW) {
            int r = t >> 2, fq = t & 3;
            const float4* xr = (const float4*)(warm +
                ((size_t)(b0 + r) * TW + s) * 32 + fq * 8);
            float4 a = __ldg(xr), b2 = __ldg(xr + 1);
            float vals[8] = {a.x, a.y, a.z, a.w, b2.x, b2.y, b2.z, b2.w};
            int p = r >> 1, hh = r & 1;
#pragma unroll
            for (int m = 0; m < 8; m++)
                sm[sxi(fq * 8 + m, p) + hh] = vals[m];
        } else {
            int r = t >> 2, fq = t & 3;
            const float* xr = autoin + ((size_t)(b0 + r) * TW + (s - TW)) * FA + fq * 6;
            int p = r >> 1, hh = r & 1;
#pragma unroll
            for (int m = 0; m < 6; m++)
                sm[sxi(fq * 6 + m, p) + hh] = __ldg(xr + m);
        }
        __syncthreads();

        // ---- y_{s-1}: output (ut0) + feedback into krows 24..31 (auto) ----
        if (s >= 1)
            y_pass(sm, swout, bo0, t, b0, ut, s - 1, s >= TW, out);
        __syncthreads();

        // ---- z GEMM: thread (w,l) -> rows 8w..8w+7, unit U, 4 gates ----
        ull acc[16];
#pragma unroll
        for (int i = 0; i < 16; i++) acc[i] = 0ULL;

#pragma unroll 8
        for (int k = 0; k < NK; k++) {
            float4 w4 = __ldg(&wp[(size_t)k * 32]);
            int sw = (k >> 2) & 31;
            ull x0 = *(const ull*)&sm[k * 64 + 2 * ((4 * w + 0) ^ sw)];
            ull x1 = *(const ull*)&sm[k * 64 + 2 * ((4 * w + 1) ^ sw)];
            ull x2 = *(const ull*)&sm[k * 64 + 2 * ((4 * w + 2) ^ sw)];
            ull x3 = *(const ull*)&sm[k * 64 + 2 * ((4 * w + 3) ^ sw)];
            ull wd0 = dup2(w4.x), wd1 = dup2(w4.y);
            ull wd2 = dup2(w4.z), wd3 = dup2(w4.w);
            fma2(acc[0],  x0, wd0); fma2(acc[1],  x0, wd1);
            fma2(acc[2],  x0, wd2); fma2(acc[3],  x0, wd3);
            fma2(acc[4],  x1, wd0); fma2(acc[5],  x1, wd1);
            fma2(acc[6],  x1, wd2); fma2(acc[7],  x1, wd3);
            fma2(acc[8],  x2, wd0); fma2(acc[9],  x2, wd1);
            fma2(acc[10], x2, wd2); fma2(acc[11], x2, wd3);
            fma2(acc[12], x3, wd0); fma2(acc[13], x3, wd1);
            fma2(acc[14], x3, wd2); fma2(acc[15], x3, wd3);
        }

        // ---- gates + cell update (c in regs) + h write to L2 ----
        float hv[8];
#pragma unroll
        for (int p4 = 0; p4 < 4; p4++) {
            float2 zi = unp(acc[4 * p4 + 0]);
            float2 zf = unp(acc[4 * p4 + 1]);
            float2 zg = unp(acc[4 * p4 + 2]);
            float2 zo = unp(acc[4 * p4 + 3]);
            {
                float ig = fsig(zi.x + bi), fg = fsig(zf.x + bf);
                float gg = fth(zg.x + bg),  og = fsig(zo.x + bo);
                float c  = fmaf(fg, cr[2 * p4], ig * gg);
                cr[2 * p4] = c; hv[2 * p4] = og * fth(c);
            }
            {
                float ig = fsig(zi.y + bi), fg = fsig(zf.y + bf);
                float gg = fth(zg.y + bg),  og = fsig(zo.y + bo);
                float c  = fmaf(fg, cr[2 * p4 + 1], ig * gg);
                cr[2 * p4 + 1] = c; hv[2 * p4 + 1] = og * fth(c);
            }
        }
        float* hd = g_hbuf[(s + 1) & 1];
#pragma unroll
        for (int i = 0; i < 8; i++)
            __stcg(&hd[(size_t)(b0 + 8 * w + i) * NH + U], hv[i]);

        // ---- grid barrier (sense = steps completed) ----
        __syncthreads();
        if (t == 0) {
            __threadfence();
            unsigned tgt = (unsigned)(s + 1);
            if (atomicAdd(&g_barctr, 1) == NCTA - 1) {
                g_barctr = 0;
                __threadfence();
                g_barsense = tgt;
            } else {
                while (g_barsense < tgt) { }
            }
            __threadfence();
        }
        __syncthreads();
    }

    // ---- tail: out[:, TT-1] = h_TT @ W_out + b_out ----
    if (ut == 0) {
        stage_h(sm, g_hbuf[TT & 1], b0, w, l);
        __syncthreads();
        y_pass(sm, swout, bo0, t, b0, 0, TT - 1, false, out);
    }
}

extern "C" void kernel_launch(void* const* d_in, const int* in_sizes, int n_in,
                              void* d_out, int out_size) {
    const float* c0     = (const float*)d_in[0];
    const float* h0     = (const float*)d_in[1];
    const float* warm   = (const float*)d_in[2];
    const float* autoin = (const float*)d_in[3];
    const float* W_ih   = (const float*)d_in[4];
    const float* W_hh   = (const float*)d_in[5];
    const float* bias   = (const float*)d_in[6];
    const float* W_out  = (const float*)d_in[7];
    const float* b_out  = (const float*)d_in[8];
    float* out = (float*)d_out;

    cudaFuncSetAttribute(lstm_main, cudaFuncAttributeMaxDynamicSharedMemorySize,
                         SMEM_BYTES);

    repack_kernel<<<(8 * NK * 128 + 255) / 256, 256>>>(W_ih, W_hh);
    lstm_main<<<NCTA, THREADS, SMEM_BYTES>>>(c0, h0, warm, autoin, bias,
                                             W_out, b_out, out);
}

// round 14
// speedup vs baseline: 1.2208x; 1.2208x over previous
#include <cuda_runtime.h>

// FullAutoLSTM, GB300 sm_103a — persistent-per-step-free design:
// 128 fully independent CTAs (8 batch rows each), 512 threads.
// Thread t: hidden unit u = t&255 (all 4 gates), rows 4*(t>>8)..+3.
// Weights gate-interleaved in global (L1/L2-resident stream), c in registers,
// h + autoregressive y feedback CTA-local in shared memory.
// fp32 GEMM via packed fma.rn.f32x2 (2 MACs per instr).

typedef unsigned long long ull;

#define TW   512
#define TA   512
#define TT   1024
#define NB   1024
#define NH   256
#define NF   32     // F = 24 auto features + 8 recurrent y
#define FA   24
#define NO   8
#define NK   288    // NF + NH
#define BT   8      // batch rows per CTA
#define NCTA (NB / BT)   // 128
#define THREADS 512
#define RS   289    // padded k-stride (float2) of the x tile

// Gate-interleaved weights: g_Wr[k*1024 + u*4 + g], g=0:i 1:f 2:g 3:o,
// source column = g*256 + u.
__device__ float g_Wr[NK * 4 * NH];

__device__ __forceinline__ void fma2(ull& a, ull x, ull w) {
    asm("fma.rn.f32x2 %0, %1, %2, %0;" : "+l"(a) : "l"(x), "l"(w));
}
__device__ __forceinline__ float2 unp(ull v) {
    float2 r; asm("mov.b64 {%0, %1}, %2;" : "=f"(r.x), "=f"(r.y) : "l"(v)); return r;
}
__device__ __forceinline__ float fsig(float x) { return 1.0f / (1.0f + __expf(-x)); }
__device__ __forceinline__ float fth(float x)  { return 2.0f / (1.0f + __expf(-2.0f * x)) - 1.0f; }

__global__ void repack_kernel(const float* __restrict__ W_ih,
                              const float* __restrict__ W_hh) {
    int i = blockIdx.x * blockDim.x + threadIdx.x;
    if (i >= NK * 4 * NH) return;
    int k = i >> 10;
    int c = i & 1023;
    int u = c >> 2;
    int g = c & 3;
    int col = g * NH + u;
    g_Wr[i] = (k < NF) ? W_ih[(size_t)k * (4 * NH) + col]
                       : W_hh[(size_t)(k - NF) * (4 * NH) + col];
}

__global__ void __launch_bounds__(THREADS, 1)
lstm_main(const float* __restrict__ c0, const float* __restrict__ h0,
          const float* __restrict__ warm,    // (B, TW, 32)
          const float* __restrict__ autoin,  // (B, TA, 24)
          const float* __restrict__ bias,    // (1024)
          const float* __restrict__ W_out,   // (256, 8)
          const float* __restrict__ b_out,   // (8)
          float* __restrict__ out)           // (B, TT, 8)
{
    // x tile, duplicated lanes for f32x2: sx[row][k] = {x, x}.
    // k in [0,FA): auto feats; [FA,NF): warm feats / y feedback; [NF,NK): h.
    __shared__ float2 sx[BT][RS];        // 18496 B
    __shared__ float  swout[NH * NO];    //  8192 B
    __shared__ float  psum[BT * NO][8];  //  2048 B

    const int t  = threadIdx.x;
    const int u  = t & 255;
    const int rh = t >> 8;               // row half: rows 4*rh .. 4*rh+3
    const int b0 = blockIdx.x * BT;

    // ---- one-time init ----
    for (int i = t; i < NH * NO; i += THREADS) swout[i] = W_out[i];
    const float bi = bias[u],           bf = bias[NH + u];
    const float bg = bias[2 * NH + u],  bo = bias[3 * NH + u];
    const float bor = b_out[t & 7];

    float cr[4];
#pragma unroll
    for (int i = 0; i < 4; i++)
        cr[i] = c0[(size_t)(b0 + 4 * rh + i) * NH + u];

    if (t < NH) {
#pragma unroll
        for (int r = 0; r < BT; r++) {
            float v = h0[(size_t)(b0 + r) * NH + t];
            sx[r][NF + t] = make_float2(v, v);
        }
    }

    const ulonglong2* __restrict__ wp =
        reinterpret_cast<const ulonglong2*>(g_Wr) + u;   // +k*NH per k

    for (int s = 0; s < TT; s++) {
        // ---- stage x_s ----
        if (s < TW) {
            if (t < NH) {
                int r = t >> 5, k = t & 31;
                float v = warm[((size_t)(b0 + r) * TW + s) * NF + k];
                sx[r][k] = make_float2(v, v);
            }
        } else {
            if (t < FA * BT) {
                int r = t / FA, k = t - r * FA;
                float v = autoin[((size_t)(b0 + r) * TA + (s - TW)) * FA + k];
                sx[r][k] = make_float2(v, v);
            }
        }
        __syncthreads();  // S1: x staged; prev h + y feedback visible

        // ---- z GEMM: acc0[r]={z_i,z_f}, acc1[r]={z_g,z_o} for 4 rows ----
        ull acc0[4], acc1[4];
#pragma unroll
        for (int r = 0; r < 4; r++) { acc0[r] = 0ULL; acc1[r] = 0ULL; }

        const ull* __restrict__ x0 = (const ull*)&sx[4 * rh + 0][0];
        const ull* __restrict__ x1 = (const ull*)&sx[4 * rh + 1][0];
        const ull* __restrict__ x2 = (const ull*)&sx[4 * rh + 2][0];
        const ull* __restrict__ x3 = (const ull*)&sx[4 * rh + 3][0];

#pragma unroll 4
        for (int k = 0; k < NK; k++) {
            ulonglong2 w = __ldg(&wp[(size_t)k * NH]);  // {wi,wf},{wg,wo}
            ull xa = x0[k], xb = x1[k], xc = x2[k], xd = x3[k];
            fma2(acc0[0], xa, w.x); fma2(acc1[0], xa, w.y);
            fma2(acc0[1], xb, w.x); fma2(acc1[1], xb, w.y);
            fma2(acc0[2], xc, w.x); fma2(acc1[2], xc, w.y);
            fma2(acc0[3], xd, w.x); fma2(acc1[3], xd, w.y);
        }

        // ---- gates + cell update (c in registers) ----
        float hv[4];
#pragma unroll
        for (int r = 0; r < 4; r++) {
            float2 zif = unp(acc0[r]);
            float2 zgo = unp(acc1[r]);
            float ig = fsig(zif.x + bi);
            float fg = fsig(zif.y + bf);
            float gg = fth(zgo.x + bg);
            float og = fsig(zgo.y + bo);
            float c  = fmaf(fg, cr[r], ig * gg);
            cr[r] = c;
            hv[r] = og * fth(c);
        }
        __syncthreads();  // S2: all GEMM reads of sx complete

#pragma unroll
        for (int r = 0; r < 4; r++)
            sx[4 * rh + r][NF + u] = make_float2(hv[r], hv[r]);
        __syncthreads();  // S3: h_s visible

        // ---- y_s = h_s @ W_out + b_out: 8 partial chunks of 32 units ----
        {
            int r = (t & 63) >> 3, o = t & 7, p = t >> 6;
            float a0 = 0.f, a1 = 0.f;
#pragma unroll
            for (int jj = 0; jj < 32; jj += 2) {
                int j = 32 * p + jj;
                a0 = fmaf(sx[r][NF + j].x,     swout[j * NO + o],       a0);
                a1 = fmaf(sx[r][NF + j + 1].x, swout[(j + 1) * NO + o], a1);
            }
            psum[t & 63][p] = a0 + a1;
        }
        __syncthreads();  // S4: partials visible

        if (t < BT * NO) {
            int r = t >> 3, o = t & 7;
            float y = bor;
#pragma unroll
            for (int p = 0; p < 8; p++) y += psum[t][p];
            out[((size_t)(b0 + r) * TT + s) * NO + o] = y;
            // Feedback into next step's input (auto phase only). Disjoint
            // from auto staging slots (k<24); ordered by next S1.
            if (s >= TW - 1 && s < TT - 1)
                sx[r][FA + o] = make_float2(y, y);
        }
    }
}

extern "C" void kernel_launch(void* const* d_in, const int* in_sizes, int n_in,
                              void* d_out, int out_size) {
    const float* c0     = (const float*)d_in[0];
    const float* h0     = (const float*)d_in[1];
    const float* warm   = (const float*)d_in[2];
    const float* autoin = (const float*)d_in[3];
    const float* W_ih   = (const float*)d_in[4];
    const float* W_hh   = (const float*)d_in[5];
    const float* bias   = (const float*)d_in[6];
    const float* W_out  = (const float*)d_in[7];
    const float* b_out  = (const float*)d_in[8];
    float* out = (float*)d_out;

    repack_kernel<<<(NK * 4 * NH + 255) / 256, 256>>>(W_ih, W_hh);
    lstm_main<<<NCTA, THREADS>>>(c0, h0, warm, autoin, bias, W_out, b_out, out);
}

// round 15
// speedup vs baseline: 1.3506x; 1.1063x over previous
#include <cuda_runtime.h>

// FullAutoLSTM, GB300 sm_103a.
// 128 independent CTAs x 256 threads. Thread t = hidden unit u (all 4 gates,
// all 8 batch rows of its CTA). Weights gate-interleaved, loaded exactly once
// per CTA per step via LDG.128; x tile duplicated {x,x} in smem with 80B
// k-stride so 8 rows = 4 LDS.128 broadcasts. c in registers; h + y feedback
// CTA-local in smem. fp32 GEMM via packed fma.rn.f32x2.

typedef unsigned long long ull;

#define TW   512
#define TA   512
#define TT   1024
#define NB   1024
#define NH   256
#define NF   32     // 24 auto features + 8 recurrent y
#define FA   24
#define NO   8
#define NK   288    // NF + NH
#define BT   8      // batch rows per CTA
#define NCTA (NB / BT)   // 128
#define THREADS 256
#define XS   20     // x-tile k-stride in floats (16 data + 4 pad = 80B)

// Gate-interleaved weights: g_Wr[k*1024 + u*4 + g], g = 0:i 1:f 2:g 3:o,
// source column = g*256 + u.  One ulonglong2 per (k,u) = {wi,wf},{wg,wo}.
__device__ float g_Wr[NK * 4 * NH];

__device__ __forceinline__ void fma2(ull& a, ull x, ull w) {
    asm("fma.rn.f32x2 %0, %1, %2, %0;" : "+l"(a) : "l"(x), "l"(w));
}
__device__ __forceinline__ float2 unp(ull v) {
    float2 r; asm("mov.b64 {%0, %1}, %2;" : "=f"(r.x), "=f"(r.y) : "l"(v)); return r;
}
__device__ __forceinline__ float fsig(float x) { return 1.0f / (1.0f + __expf(-x)); }
__device__ __forceinline__ float fth(float x)  { return 2.0f / (1.0f + __expf(-2.0f * x)) - 1.0f; }

__global__ void repack_kernel(const float* __restrict__ W_ih,
                              const float* __restrict__ W_hh) {
    int i = blockIdx.x * blockDim.x + threadIdx.x;
    if (i >= NK * 4 * NH) return;
    int k = i >> 10;
    int c = i & 1023;
    int u = c >> 2;
    int g = c & 3;
    int col = g * NH + u;
    g_Wr[i] = (k < NF) ? W_ih[(size_t)k * (4 * NH) + col]
                       : W_hh[(size_t)(k - NF) * (4 * NH) + col];
}

__global__ void __launch_bounds__(THREADS, 1)
lstm_main(const float* __restrict__ c0, const float* __restrict__ h0,
          const float* __restrict__ warm,    // (B, TW, 32)
          const float* __restrict__ autoin,  // (B, TA, 24)
          const float* __restrict__ bias,    // (1024)
          const float* __restrict__ W_out,   // (256, 8)
          const float* __restrict__ b_out,   // (8)
          float* __restrict__ out)           // (B, TT, 8)
{
    // x tile: sx[k*XS + 2r] = {x_rk, x_rk} (float2). 80B per k row:
    // 16B-aligned for LDS.128/STS.128, pad keeps h-store banks conflict-free.
    // k in [0,FA): auto feats; [FA,NF): warm feats / y feedback; [NF,NK): h.
    __shared__ float sx[NK * XS];        // 23040 B
    __shared__ float swout[NH * NO];     //  8192 B
    __shared__ float psum[BT * NO][5];   //  1280 B

    const int t  = threadIdx.x;          // == hidden unit u
    const int b0 = blockIdx.x * BT;

    for (int i = t; i < NH * NO; i += THREADS) swout[i] = W_out[i];
    const float bi = bias[t],           bf = bias[NH + t];
    const float bg = bias[2 * NH + t],  bo = bias[3 * NH + t];
    const float bor = b_out[t & 7];

    float cr[BT];
#pragma unroll
    for (int r = 0; r < BT; r++) {
        cr[r] = c0[(size_t)(b0 + r) * NH + t];
        float v = h0[(size_t)(b0 + r) * NH + t];
        *(float2*)&sx[(NF + t) * XS + 2 * r] = make_float2(v, v);
    }

    const ulonglong2* __restrict__ wp =
        reinterpret_cast<const ulonglong2*>(g_Wr) + t;   // +k*256 per k

    for (int s = 0; s < TT; s++) {
        // ---- stage x_s ----
        if (s < TW) {
            int r = t >> 5, k = t & 31;
            float v = warm[((size_t)(b0 + r) * TW + s) * NF + k];
            *(float2*)&sx[k * XS + 2 * r] = make_float2(v, v);
        } else if (t < FA * BT) {
            int r = t / FA, k = t - r * FA;
            float v = autoin[((size_t)(b0 + r) * TA + (s - TW)) * FA + k];
            *(float2*)&sx[k * XS + 2 * r] = make_float2(v, v);
        }
        __syncthreads();  // S1: x staged; h + y feedback visible

        // ---- z GEMM: aif[r]={z_i,z_f}, ago[r]={z_g,z_o}, rows 0..7 ----
        ull aif[BT], ago[BT];
#pragma unroll
        for (int r = 0; r < BT; r++) { aif[r] = 0ULL; ago[r] = 0ULL; }

#pragma unroll 8
        for (int k = 0; k < NK; k++) {
            ulonglong2 w2 = __ldg(&wp[(size_t)k * 256]);  // {wi,wf},{wg,wo}
            const ulonglong2* xk = (const ulonglong2*)&sx[k * XS];
            ulonglong2 x01 = xk[0];   // {x_r0 dup, x_r1 dup}
            ulonglong2 x23 = xk[1];
            ulonglong2 x45 = xk[2];
            ulonglong2 x67 = xk[3];
            fma2(aif[0], x01.x, w2.x); fma2(ago[0], x01.x, w2.y);
            fma2(aif[1], x01.y, w2.x); fma2(ago[1], x01.y, w2.y);
            fma2(aif[2], x23.x, w2.x); fma2(ago[2], x23.x, w2.y);
            fma2(aif[3], x23.y, w2.x); fma2(ago[3], x23.y, w2.y);
            fma2(aif[4], x45.x, w2.x); fma2(ago[4], x45.x, w2.y);
            fma2(aif[5], x45.y, w2.x); fma2(ago[5], x45.y, w2.y);
            fma2(aif[6], x67.x, w2.x); fma2(ago[6], x67.x, w2.y);
            fma2(aif[7], x67.y, w2.x); fma2(ago[7], x67.y, w2.y);
        }

        // ---- gates + cell update (c in registers) ----
        float hv[BT];
#pragma unroll
        for (int r = 0; r < BT; r++) {
            float2 zif = unp(aif[r]);
            float2 zgo = unp(ago[r]);
            float ig = fsig(zif.x + bi);
            float fg = fsig(zif.y + bf);
            float gg = fth(zgo.x + bg);
            float og = fsig(zgo.y + bo);
            float c  = fmaf(fg, cr[r], ig * gg);
            cr[r] = c;
            hv[r] = og * fth(c);
        }
        __syncthreads();  // S2: all GEMM smem reads complete

        // h_s -> sx (4 STS.128, conflict-free thanks to 80B stride)
#pragma unroll
        for (int rp = 0; rp < 4; rp++) {
            *(float4*)&sx[(NF + t) * XS + 4 * rp] =
                make_float4(hv[2 * rp], hv[2 * rp], hv[2 * rp + 1], hv[2 * rp + 1]);
        }
        __syncthreads();  // S3: h_s visible

        // ---- y_s = h_s @ W_out + b_out: 4 partial chunks of 64 units ----
        {
            int combo = t & 63;           // (r, o)
            int p = t >> 6;               // 0..3 -> unit chunk of 64
            int r = combo >> 3, o = combo & 7;
            float a0 = 0.f, a1 = 0.f;
#pragma unroll 8
            for (int jj = 0; jj < 64; jj += 2) {
                int j = 64 * p + jj;
                a0 = fmaf(sx[(NF + j) * XS + 2 * r],     swout[j * NO + o],       a0);
                a1 = fmaf(sx[(NF + j + 1) * XS + 2 * r], swout[(j + 1) * NO + o], a1);
            }
            psum[combo][p] = a0 + a1;
        }
        __syncthreads();  // S4: partials visible

        if (t < BT * NO) {
            int r = t >> 3, o = t & 7;
            float y = bor + ((psum[t][0] + psum[t][1]) +
                             (psum[t][2] + psum[t][3]));
            out[((size_t)(b0 + r) * TT + s) * NO + o] = y;
            // Autoregressive feedback into next step's input slots [24,32).
            // Disjoint from auto staging (k < 24); ordered by next S1.
            if (s >= TW - 1 && s < TT - 1)
                *(float2*)&sx[(FA + o) * XS + 2 * r] = make_float2(y, y);
        }
    }
}

extern "C" void kernel_launch(void* const* d_in, const int* in_sizes, int n_in,
                              void* d_out, int out_size) {
    const float* c0     = (const float*)d_in[0];
    const float* h0     = (const float*)d_in[1];
    const float* warm   = (const float*)d_in[2];
    const float* autoin = (const float*)d_in[3];
    const float* W_ih   = (const float*)d_in[4];
    const float* W_hh   = (const float*)d_in[5];
    const float* bias   = (const float*)d_in[6];
    const float* W_out  = (const float*)d_in[7];
    const float* b_out  = (const float*)d_in[8];
    float* out = (float*)d_out;

    repack_kernel<<<(NK * 4 * NH + 255) / 256, 256>>>(W_ih, W_hh);
    lstm_main<<<NCTA, THREADS>>>(c0, h0, warm, autoin, bias, W_out, b_out, out);
}